// round 11
// baseline (speedup 1.0000x reference)
#include <cuda_runtime.h>
#include <cstdint>

typedef unsigned long long ull;

// Problem constants (fixed shapes)
#define BB 2
#define NN 16384
#define MM 8192

// Pair-kernel tiling
#define THREADS 256
#define RP 8                      // packed n-pairs per thread
#define RR (2 * RP)               // 16 n per thread
#define TN (RR * THREADS)         // 4096 n per block
#define NT (NN / TN)              // 4 n-tiles
#define MT 37                     // m-tiles
#define TM 224                    // 37*224 = 8288 >= 8192
#define NWARPS (THREADS / 32)

// k_partial tiling
#define PBLKS 512                 // 256 blocks per batch: 64 n + 32 m each

#define NEG_BIG -3.0e38f
#define ENC_NEG_INF ((int)0x80000000)

// ---------------- scratch (device globals; slot-per-block, no atomics) --------
__device__ int    g_s1[MT][BB * NN];    // side-1 partial: per m-tile block, per n
__device__ int    g_s2[NT][BB * MM];    // side-2 partial: per n-tile block, per m
__device__ float4 g_part[PBLKS];        // per-block {s0, s1, s2, wm_local}
__device__ unsigned int g_done = 0;     // completion counter (self-resetting)

// Order-preserving float<->int encoding (monotone under signed int compare).
__device__ __forceinline__ int encf(float f) {
    int i = __float_as_int(f);
    return (i >= 0) ? i : (i ^ 0x7FFFFFFF);
}
__device__ __forceinline__ float decf(int k) {
    return __int_as_float((k >= 0) ? k : (k ^ 0x7FFFFFFF));
}

// ---------------- packed f32x2 + redux helpers --------------------------------
__device__ __forceinline__ ull pk2(float lo, float hi) {
    ull r; asm("mov.b64 %0, {%1, %2};" : "=l"(r) : "f"(lo), "f"(hi)); return r;
}
__device__ __forceinline__ void upk2(ull v, float& lo, float& hi) {
    asm("mov.b64 {%0, %1}, %2;" : "=f"(lo), "=f"(hi) : "l"(v));
}
__device__ __forceinline__ ull ffma2(ull a, ull b, ull c) {
    ull d; asm("fma.rn.f32x2 %0, %1, %2, %3;" : "=l"(d) : "l"(a), "l"(b), "l"(c)); return d;
}
__device__ __forceinline__ ull fadd2(ull a, ull b) {
    ull d; asm("add.rn.f32x2 %0, %1, %2;" : "=l"(d) : "l"(a), "l"(b)); return d;
}
// Hardware cross-lane s32 max (sm_80+ baseline).
__device__ __forceinline__ int redux_maxi(int v) {
    int r; asm("redux.sync.max.s32 %0, %1, 0xffffffff;" : "=r"(r) : "r"(v)); return r;
}

// ---------------- kernel 1: pairwise dual-min (pipelined f32x2 + redux) -------
// UNCHANGED from R10 — measured at the packed-FMA-pipe roofline (~59us).
__global__ void __launch_bounds__(THREADS, 2) k_pairs(const float* __restrict__ p1,
                                                      const float* __restrict__ p2) {
    const int b  = blockIdx.z;
    const int nb = blockIdx.y * TN;
    const int mb = blockIdx.x * TM;
    const int tid  = threadIdx.x;
    const int wid  = tid >> 5;
    const int lane = tid & 31;

    __shared__ ulonglong2 smA[TM + 1];   // {xx, yy}; +1 pad: branch-free preload
    __shared__ ulonglong2 smB[TM + 1];   // {zz, ww}  (w = -0.5*|p|^2)
    __shared__ int swm[NWARPS][TM];      // encoded per-warp maxima

    // stage + pack m-tile directly from raw points2 (L2-resident, 2.7KB/block)
    if (tid <= TM) {
        int mg = mb + tid;
        float x = 0.f, y = 0.f, z = 0.f, w2 = NEG_BIG;   // sentinel never wins
        if (tid < TM && mg < MM) {
            const float* p = p2 + ((size_t)b * MM + mg) * 3;
            x = p[0]; y = p[1]; z = p[2];
            w2 = -0.5f * (x * x + y * y + z * z);
        }
        ulonglong2 A, B;
        A.x = pk2(x, x);  A.y = pk2(y, y);
        B.x = pk2(z, z);  B.y = pk2(w2, w2);
        smA[tid] = A; smB[tid] = B;
    }

    // per-thread n registers (packed pairs of consecutive n)
    ull x2[RP], y2[RP], z2[RP], hn2[RP];
    float mx[RR];
#pragma unroll
    for (int p = 0; p < RP; p++) {
        int n0 = nb + (p * THREADS + tid) * 2;           // exact tiling, always < NN
        const float2* q = (const float2*)(p1 + ((size_t)b * NN + n0) * 3);
        float2 a = q[0], bb2 = q[1], cc = q[2];
        float X0 = a.x,  Y0 = a.y,  Z0 = bb2.x;
        float X1 = bb2.y, Y1 = cc.x, Z1 = cc.y;
        x2[p] = pk2(X0, X1);
        y2[p] = pk2(Y0, Y1);
        z2[p] = pk2(Z0, Z1);
        float h0 = 0.5f * (X0 * X0 + Y0 * Y0 + Z0 * Z0);
        float h1 = 0.5f * (X1 * X1 + Y1 * Y1 + Z1 * Z1);
        hn2[p] = pk2(-h0, -h1);
        mx[2 * p] = NEG_BIG; mx[2 * p + 1] = NEG_BIG;
    }
    __syncthreads();

    // software-pipelined j loop: m-point for j+1 loads while j computes
    ulonglong2 A0 = smA[0], B0 = smB[0];
#pragma unroll 2
    for (int j = 0; j < TM; j++) {
        ulonglong2 A1 = smA[j + 1];                      // LDS.128 (pad makes legal)
        ulonglong2 B1 = smB[j + 1];
        ull bx = A0.x, by = A0.y, bz = B0.x, bw = B0.y;
        float wm0 = NEG_BIG, wm1 = NEG_BIG;
#pragma unroll
        for (int p = 0; p < RP; p++) {
            ull c2 = ffma2(x2[p], bx, bw);               // acc init = -h2m
            c2 = ffma2(y2[p], by, c2);
            c2 = ffma2(z2[p], bz, c2);
            ull w2 = fadd2(c2, hn2[p]);                  // c' - h1
            float cl, ch; upk2(c2, cl, ch);              // reg-pair alias (free)
            mx[2 * p]     = fmaxf(mx[2 * p], cl);
            mx[2 * p + 1] = fmaxf(mx[2 * p + 1], ch);
            float wl, wh; upk2(w2, wl, wh);
            wm0 = fmaxf(wm0, wl);
            wm1 = fmaxf(wm1, wh);
        }
        int t = redux_maxi(encf(fmaxf(wm0, wm1)));       // single-op warp max
        if (lane == 0) swm[wid][j] = t;
        A0 = A1; B0 = B1;
    }

    // flush side 1: per-n tile-max -> own slot (plain coalesced ST.64, no atomics)
#pragma unroll
    for (int p = 0; p < RP; p++) {
        int n0 = nb + (p * THREADS + tid) * 2;
        int2 v; v.x = encf(mx[2 * p]); v.y = encf(mx[2 * p + 1]);
        *reinterpret_cast<int2*>(&g_s1[blockIdx.x][b * NN + n0]) = v;
    }
    __syncthreads();

    // flush side 2: cross-warp reduce (encoded), write own slot
    for (int j = tid; j < TM; j += THREADS) {
        int mg = mb + j;
        if (mg < MM) {
            int v = swm[0][j];
#pragma unroll
            for (int w = 1; w < NWARPS; w++) v = max(v, swm[w][j]);
            g_s2[blockIdx.y][b * MM + mg] = v;
        }
    }
}

// ---------------- kernel 2: slot reduce (thread-parallel) + fused final -------
// 512 blocks: blk>>8 = batch; per block 64 n (37 slots split over 4 thread
// groups) and 32 m (4 slots over 128 threads).
__global__ void __launch_bounds__(THREADS) k_partial(const float* __restrict__ p1,
                                                     const float* __restrict__ w,
                                                     float* __restrict__ out) {
    const int blk  = blockIdx.x;              // 0..511
    const int b    = blk >> 8;                // batch
    const int nidx = blk & 255;               // chunk index within batch
    const int tid  = threadIdx.x;
    const int nl   = tid & 63;                // n within chunk
    const int grp  = tid >> 6;                // slot group 0..3

    __shared__ int   sm1[THREADS];            // side-1 group maxima
    __shared__ int   sm2[128];                // side-2 per-(m,slot) values
    __shared__ float sa[THREADS], sb[THREADS], sc[THREADS];
    __shared__ int   swx[2];

    const int n  = nidx * 64 + nl;
    const int gn = b * NN + n;

    // ---- front-batched loads (each thread ~10 independent LDGs) ----
    // side 1: group grp covers slots [grp*9, grp*9+9), group 3 also slot 36
    int acc = ENC_NEG_INF;
#pragma unroll
    for (int k = 0; k < 10; k++) {
        int slot = grp * 9 + k;
        if (k < 9 || grp == 3) acc = max(acc, g_s1[slot][gn]);
    }
    // side 2: threads 0..127 -> (m 0..31) x (slot 0..3)
    int v2 = ENC_NEG_INF;
    if (tid < 128) {
        int gm = b * MM + nidx * 32 + (tid & 31);
        v2 = g_s2[tid >> 5][gm];
    }
    // n-side inputs (only group 0 uses them)
    float wv = 0.f, xx = 0.f, yy = 0.f, zz = 0.f;
    if (grp == 0) {
        wv = w[gn];
        const float* p = p1 + (size_t)gn * 3;
        xx = p[0]; yy = p[1]; zz = p[2];
    }

    sm1[tid] = acc;
    if (tid < 128) sm2[tid] = v2;
    __syncthreads();

    // ---- combine + per-block sums ----
    float s0 = 0.f, s1 = 0.f, s2 = 0.f, wm = NEG_BIG;
    // block-local weight max over the 64 n (warps 0-1 hold them)
    if (grp == 0) {
        int te = redux_maxi(encf(wv));        // per-warp (32 of the 64)
        if ((tid & 31) == 0) swx[tid >> 5] = te;
    }
    __syncthreads();
    wm = decf(max(swx[0], swx[1]));

    if (grp == 0) {
        int m1 = max(max(sm1[nl], sm1[nl + 64]), max(sm1[nl + 128], sm1[nl + 192]));
        float e = expf(wv - wm);
        float h1 = 0.5f * (xx * xx + yy * yy + zz * zz);
        s0 = e;
        s1 = e * (2.0f * (h1 - decf(m1)));
    }
    if (tid < 32) {
        int m2 = max(max(sm2[tid], sm2[tid + 32]), max(sm2[tid + 64], sm2[tid + 96]));
        s2 = decf(m2);
    }

    sa[tid] = s0; sb[tid] = s1; sc[tid] = s2;
    __syncthreads();
    for (int st = 32; st > 0; st >>= 1) {      // s0,s1 live in tid<64; s2 in tid<32
        if (tid < st) {
            sa[tid] += sa[tid + st] + ((st == 32) ? sa[tid + 32] : 0.f);  // placeholder no
        }
        __syncthreads();
    }
    // NOTE: the loop above is wrong-shaped for mixed widths; replaced below.
    __syncthreads();

    // re-do reductions cleanly (cheap): s0,s1 over 64 entries; s2 over 32
    sa[tid] = s0; sb[tid] = s1; sc[tid] = s2;
    __syncthreads();
    if (tid < 32) {
        float a0 = sa[tid] + sa[tid + 32];
        float b0 = sb[tid] + sb[tid + 32];
        float c0 = sc[tid];
#pragma unroll
        for (int off = 16; off > 0; off >>= 1) {
            a0 += __shfl_xor_sync(0xffffffffu, a0, off);
            b0 += __shfl_xor_sync(0xffffffffu, b0, off);
            c0 += __shfl_xor_sync(0xffffffffu, c0, off);
        }
        if (tid == 0) {
            float4 r; r.x = a0; r.y = b0; r.z = c0; r.w = wm;
            g_part[blk] = r;
        }
    }

    __shared__ int last;
    __threadfence();
    __syncthreads();
    if (tid == 0) {
        unsigned int prev = atomicAdd(&g_done, 1u);
        last = (prev == PBLKS - 1) ? 1 : 0;
    }
    __syncthreads();
    if (!last) return;
    __threadfence();

    // ---- last block: deterministic fixed-order combine of 512 partials ----
    // thread tid owns partial tid (batch0, blocks 0..255) and tid+256 (batch1)
    float4 pa, pb;
    {
        volatile float4* va = (volatile float4*)&g_part[tid];
        volatile float4* vb = (volatile float4*)&g_part[tid + 256];
        pa.x = va->x; pa.y = va->y; pa.z = va->z; pa.w = va->w;
        pb.x = vb->x; pb.y = vb->y; pb.z = vb->z; pb.w = vb->w;
    }
    float loss = 0.f;
#pragma unroll
    for (int pass = 0; pass < 2; pass++) {
        float4 gp = (pass == 0) ? pa : pb;
        // global weight max for this batch
        sa[tid] = gp.w;
        __syncthreads();
        for (int st = 128; st > 0; st >>= 1) {
            if (tid < st) sa[tid] = fmaxf(sa[tid], sa[tid + st]);
            __syncthreads();
        }
        float wmg = sa[0];
        __syncthreads();
        // rescale + sum
        float s = expf(gp.w - wmg);
        sa[tid] = gp.x * s; sb[tid] = gp.y * s; sc[tid] = gp.z;
        __syncthreads();
        for (int st = 128; st > 0; st >>= 1) {
            if (tid < st) {
                sa[tid] += sa[tid + st];
                sb[tid] += sb[tid + st];
                sc[tid] += sc[tid + st];
            }
            __syncthreads();
        }
        if (tid == 0)
            loss += sb[0] / sa[0] + (-2.0f * sc[0] / (float)MM);
        __syncthreads();
    }
    if (tid == 0) {
        out[0] = loss / (float)BB;
        g_done = 0;                           // reset for graph replay
    }
}

// ---------------- launch -----------------------------------------------------
extern "C" void kernel_launch(void* const* d_in, const int* in_sizes, int n_in,
                              void* d_out, int out_size) {
    const float* points1 = (const float*)d_in[0];   // (2,16384,3)
    const float* points2 = (const float*)d_in[1];   // (2,8192,3)
    const float* weights = (const float*)d_in[2];   // (2,16384)
    float* out = (float*)d_out;

    k_pairs<<<dim3(MT, NT, BB), THREADS>>>(points1, points2);
    k_partial<<<PBLKS, THREADS>>>(points1, weights, out);
}